// round 6
// baseline (speedup 1.0000x reference)
#include <cuda_runtime.h>
#include <math.h>
#include <stdint.h>

// [B,N,L,H,E] = [4,4,1024,8,64] fp32. For fixed (b,n,h): row l at bn*L*H*E + l*H*E + h*E,
// contiguous E=64 floats, stride H*E=512 floats between consecutive l.

#define Bc 4
#define Nc 4
#define Lc 1024
#define Hc 8
#define Ec 64
#define ROWSTRIDE (Hc*Ec)

#define LTILE 128
#define STILE 64
#define NTHREADS 256
#define PADA 68            // pitch (words) sQ/sK: bank = 4*row+col -> conflict-free frags
#define PADV 72            // pitch (words) sV:   bank = 8t+g      -> conflict-free frags

#define SQ_W (LTILE*PADA)                       // 8704
#define SK_W (STILE*PADA)                       // 4352
#define SV_W (STILE*PADV)                       // 4608
#define SMEM_WORDS (SQ_W + 2*SK_W + 2*SV_W)     // 26624 words = 106496 B

static __device__ __forceinline__ uint32_t f2tf(float f) {
    uint32_t u; asm("cvt.rna.tf32.f32 %0, %1;" : "=r"(u) : "f"(f)); return u;
}

// D(16x8,f32) += A(16x8,tf32,row) * B(8x8,tf32,col)
static __device__ __forceinline__ void mma8(float* c, const uint32_t* a, const uint32_t* b) {
    asm volatile(
        "mma.sync.aligned.m16n8k8.row.col.f32.tf32.tf32.f32 "
        "{%0,%1,%2,%3}, {%4,%5,%6,%7}, {%8,%9}, {%0,%1,%2,%3};"
        : "+f"(c[0]), "+f"(c[1]), "+f"(c[2]), "+f"(c[3])
        : "r"(a[0]), "r"(a[1]), "r"(a[2]), "r"(a[3]), "r"(b[0]), "r"(b[1]));
}

// 4x (8 rows x 16B) matrices; over 32-bit data this yields tf32 fragments directly.
static __device__ __forceinline__ void ldsm4(uint32_t* r, uint32_t addr) {
    asm volatile("ldmatrix.sync.aligned.m8n8.x4.b16 {%0,%1,%2,%3}, [%4];"
                 : "=r"(r[0]), "=r"(r[1]), "=r"(r[2]), "=r"(r[3]) : "r"(addr));
}

extern "C" __global__ void __launch_bounds__(NTHREADS, 2)
attn_tc2_kernel(const float* __restrict__ Q, const float* __restrict__ K,
                const float* __restrict__ V, float* __restrict__ O)
{
    extern __shared__ uint32_t smem[];
    uint32_t* sQ = smem;
    uint32_t* sKp[2] = { smem + SQ_W,            smem + SQ_W + SK_W };
    uint32_t* sVp[2] = { smem + SQ_W + 2*SK_W,   smem + SQ_W + 2*SK_W + SV_W };

    const int tid  = threadIdx.x;
    const int w    = tid >> 5;
    const int lane = tid & 31;
    const int g    = lane >> 2;
    const int t    = lane & 3;

    const int qt  = blockIdx.x;             // 0..7
    const int bnh = blockIdx.y;             // 0..127
    const int h   = bnh & (Hc - 1);
    const int bn  = bnh >> 3;
    const size_t base = (size_t)bn * Lc * ROWSTRIDE + (size_t)h * Ec;
    const int q0 = qt * LTILE;

    const int lr = tid >> 4;                // 0..15 (fill row)
    const int le = (tid & 15) << 2;         // 0,4,..,60 (fill col)

    // ---- prologue: Q tile (scaled, tf32) + K/V tile 0 ----
    #pragma unroll
    for (int it = 0; it < LTILE / 16; ++it) {
        int r = it * 16 + lr;
        float4 v = *(const float4*)(Q + base + (size_t)(q0 + r) * ROWSTRIDE + le);
        uint4 u;
        u.x = f2tf(v.x * 0.125f); u.y = f2tf(v.y * 0.125f);
        u.z = f2tf(v.z * 0.125f); u.w = f2tf(v.w * 0.125f);
        *(uint4*)(&sQ[r * PADA + le]) = u;
    }
    #pragma unroll
    for (int it = 0; it < STILE / 16; ++it) {
        int r = it * 16 + lr;
        size_t ga = base + (size_t)r * ROWSTRIDE + le;
        float4 kv = *(const float4*)(K + ga);
        float4 vv = *(const float4*)(V + ga);
        uint4 uk, uv;
        uk.x = f2tf(kv.x); uk.y = f2tf(kv.y); uk.z = f2tf(kv.z); uk.w = f2tf(kv.w);
        uv.x = f2tf(vv.x); uv.y = f2tf(vv.y); uv.z = f2tf(vv.z); uv.w = f2tf(vv.w);
        *(uint4*)(&sKp[0][r * PADA + le]) = uk;
        *(uint4*)(&sVp[0][r * PADV + le]) = uv;
    }
    __syncthreads();

    // ---- per-lane ldmatrix addresses ----
    const int rw  = w * 16;
    const int mat  = lane >> 3, mrow = lane & 7;
    const uint32_t q_ls = (uint32_t)__cvta_generic_to_shared(sQ)
        + (uint32_t)(((rw + mrow + (mat & 1) * 8) * PADA + (mat >> 1) * 4) << 2);
    const uint32_t kbase[2] = { (uint32_t)__cvta_generic_to_shared(sKp[0]),
                                (uint32_t)__cvta_generic_to_shared(sKp[1]) };
    uint32_t k_off[4];
    #pragma unroll
    for (int np = 0; np < 4; ++np)
        k_off[np] = (uint32_t)(((np * 16 + ((lane >> 4) << 3) + mrow) * PADA
                                + ((lane >> 3) & 1) * 4) << 2);

    float o[8][4];
    #pragma unroll
    for (int nt = 0; nt < 8; ++nt) { o[nt][0]=0.f; o[nt][1]=0.f; o[nt][2]=0.f; o[nt][3]=0.f; }
    float m0 = -INFINITY, m1 = -INFINITY, l0 = 0.f, l1 = 0.f;

    const int r0g = q0 + rw + g;
    const int nkt = 2 * qt + 2;
    const int srcA = (lane & ~3) | (t >> 1);

    for (int kt = 0; kt < nkt; ++kt) {
        const int cur = kt & 1, nxt = cur ^ 1;
        const bool haveNext = (kt + 1 < nkt);
        const int k0 = kt * STILE;
        const bool active = (k0 <= q0 + rw + 15);

        // prefetch next K tile (latency hidden behind GEMM1)
        float4 kreg[4];
        if (haveNext) {
            const int k0n = k0 + STILE;
            #pragma unroll
            for (int it = 0; it < 4; ++it)
                kreg[it] = *(const float4*)(K + base + (size_t)(k0n + it*16 + lr) * ROWSTRIDE + le);
        }

        // ---- GEMM1: S(16x64) = Q_w * K^T ----
        float s[8][4];
        if (active) {
            #pragma unroll
            for (int nt = 0; nt < 8; ++nt) { s[nt][0]=0.f; s[nt][1]=0.f; s[nt][2]=0.f; s[nt][3]=0.f; }
            const uint32_t kb = kbase[cur];
            #pragma unroll
            for (int kk = 0; kk < 8; ++kk) {
                uint32_t a[4]; ldsm4(a, q_ls + kk * 32);
                #pragma unroll
                for (int np = 0; np < 4; ++np) {
                    uint32_t b[4]; ldsm4(b, kb + k_off[np] + kk * 32);
                    mma8(s[2*np],     a, b);
                    mma8(s[2*np + 1], a, b + 2);
                }
            }
        }

        // drain K prefetch into the other buffer; start V prefetch
        float4 vreg[4];
        if (haveNext) {
            #pragma unroll
            for (int it = 0; it < 4; ++it) {
                uint4 u;
                u.x = f2tf(kreg[it].x); u.y = f2tf(kreg[it].y);
                u.z = f2tf(kreg[it].z); u.w = f2tf(kreg[it].w);
                *(uint4*)(&sKp[nxt][(it*16 + lr) * PADA + le]) = u;
            }
            const int k0n = k0 + STILE;
            #pragma unroll
            for (int it = 0; it < 4; ++it)
                vreg[it] = *(const float4*)(V + base + (size_t)(k0n + it*16 + lr) * ROWSTRIDE + le);
        }

        if (active) {
            // ---- causal mask (S pre-scaled via Q) ----
            if (k0 + STILE - 1 > q0 + rw) {
                #pragma unroll
                for (int nt = 0; nt < 8; ++nt) {
                    int c = k0 + nt * 8 + 2 * t;
                    if (c     > r0g)     s[nt][0] = -INFINITY;
                    if (c + 1 > r0g)     s[nt][1] = -INFINITY;
                    if (c     > r0g + 8) s[nt][2] = -INFINITY;
                    if (c + 1 > r0g + 8) s[nt][3] = -INFINITY;
                }
            }
            // ---- online softmax ----
            float mx0 = -INFINITY, mx1 = -INFINITY;
            #pragma unroll
            for (int nt = 0; nt < 8; ++nt) {
                mx0 = fmaxf(mx0, fmaxf(s[nt][0], s[nt][1]));
                mx1 = fmaxf(mx1, fmaxf(s[nt][2], s[nt][3]));
            }
            mx0 = fmaxf(mx0, __shfl_xor_sync(0xffffffffu, mx0, 1));
            mx0 = fmaxf(mx0, __shfl_xor_sync(0xffffffffu, mx0, 2));
            mx1 = fmaxf(mx1, __shfl_xor_sync(0xffffffffu, mx1, 1));
            mx1 = fmaxf(mx1, __shfl_xor_sync(0xffffffffu, mx1, 2));

            float mn0 = fmaxf(m0, mx0), mn1 = fmaxf(m1, mx1);
            float cr0 = __expf(m0 - mn0), cr1 = __expf(m1 - mn1);

            float ps0 = 0.f, ps1 = 0.f;
            #pragma unroll
            for (int nt = 0; nt < 8; ++nt) {
                s[nt][0] = __expf(s[nt][0] - mn0);
                s[nt][1] = __expf(s[nt][1] - mn0);
                s[nt][2] = __expf(s[nt][2] - mn1);
                s[nt][3] = __expf(s[nt][3] - mn1);
                ps0 += s[nt][0] + s[nt][1];
                ps1 += s[nt][2] + s[nt][3];
            }
            ps0 += __shfl_xor_sync(0xffffffffu, ps0, 1);
            ps0 += __shfl_xor_sync(0xffffffffu, ps0, 2);
            ps1 += __shfl_xor_sync(0xffffffffu, ps1, 1);
            ps1 += __shfl_xor_sync(0xffffffffu, ps1, 2);

            l0 = l0 * cr0 + ps0;  l1 = l1 * cr1 + ps1;
            m0 = mn0;             m1 = mn1;
            #pragma unroll
            for (int nt = 0; nt < 8; ++nt) {
                o[nt][0] *= cr0; o[nt][1] *= cr0; o[nt][2] *= cr1; o[nt][3] *= cr1;
            }
        }

        // drain V prefetch (before GEMM2 so vreg's live range ends early)
        if (haveNext) {
            #pragma unroll
            for (int it = 0; it < 4; ++it) {
                uint4 u;
                u.x = f2tf(vreg[it].x); u.y = f2tf(vreg[it].y);
                u.z = f2tf(vreg[it].z); u.w = f2tf(vreg[it].w);
                *(uint4*)(&sVp[nxt][(it*16 + lr) * PADV + le]) = u;
            }
        }

        // ---- GEMM2: O += P * V ; A fragment built by in-register shuffle ----
        if (active) {
            const uint32_t* vb = sVp[cur];
            const bool odd = (t & 1);
            #pragma unroll
            for (int kk = 0; kk < 8; ++kk) {
                float u0 = __shfl_sync(0xffffffffu, s[kk][0], srcA);
                float u1 = __shfl_sync(0xffffffffu, s[kk][1], srcA);
                float u2 = __shfl_sync(0xffffffffu, s[kk][2], srcA);
                float u3 = __shfl_sync(0xffffffffu, s[kk][3], srcA);
                float x0 = __shfl_sync(0xffffffffu, s[kk][0], srcA + 2);
                float x1 = __shfl_sync(0xffffffffu, s[kk][1], srcA + 2);
                float x2 = __shfl_sync(0xffffffffu, s[kk][2], srcA + 2);
                float x3 = __shfl_sync(0xffffffffu, s[kk][3], srcA + 2);
                uint32_t a[4];
                a[0] = f2tf(odd ? u1 : u0);   // P[g   ][8kk+t]
                a[1] = f2tf(odd ? u3 : u2);   // P[g+8 ][8kk+t]
                a[2] = f2tf(odd ? x1 : x0);   // P[g   ][8kk+t+4]
                a[3] = f2tf(odd ? x3 : x2);   // P[g+8 ][8kk+t+4]
                const uint32_t* vrow = vb + (kk * 8 + t) * PADV + g;
                #pragma unroll
                for (int nt = 0; nt < 8; ++nt) {
                    uint32_t b[2] = { vrow[nt * 8], vrow[nt * 8 + 4 * PADV] };
                    mma8(o[nt], a, b);
                }
            }
        }

        __syncthreads();   // all reads of cur done + all writes of nxt done
    }

    // ---- epilogue ----
    const float inv0 = 1.f / l0, inv1 = 1.f / l1;
    const size_t ro0 = base + (size_t)r0g * ROWSTRIDE;
    const size_t ro1 = ro0 + (size_t)8 * ROWSTRIDE;
    #pragma unroll
    for (int nt = 0; nt < 8; ++nt) {
        float2 v0; v0.x = o[nt][0] * inv0; v0.y = o[nt][1] * inv0;
        float2 v1; v1.x = o[nt][2] * inv1; v1.y = o[nt][3] * inv1;
        *(float2*)(O + ro0 + nt * 8 + 2 * t) = v0;
        *(float2*)(O + ro1 + nt * 8 + 2 * t) = v1;
    }
}

extern "C" void kernel_launch(void* const* d_in, const int* in_sizes, int n_in,
                              void* d_out, int out_size)
{
    const float* Q = (const float*)d_in[0];
    const float* K = (const float*)d_in[1];
    const float* V = (const float*)d_in[2];
    float* O = (float*)d_out;

    const int smem_bytes = SMEM_WORDS * (int)sizeof(uint32_t);   // 106496
    cudaFuncSetAttribute(attn_tc2_kernel,
                         cudaFuncAttributeMaxDynamicSharedMemorySize, smem_bytes);

    dim3 grid(Lc / LTILE, Bc * Nc * Hc);    // (8, 128)
    attn_tc2_kernel<<<grid, NTHREADS, smem_bytes>>>(Q, K, V, O);
}

// round 8
// speedup vs baseline: 2.0542x; 2.0542x over previous
#include <cuda_runtime.h>
#include <cuda_fp16.h>
#include <math.h>
#include <stdint.h>

// [B,N,L,H,E] = [4,4,1024,8,64] fp32. For fixed (b,n,h): row l at bn*L*H*E + l*H*E + h*E,
// contiguous E=64 floats, stride H*E=512 floats between consecutive l.

#define Bc 4
#define Nc 4
#define Lc 1024
#define Hc 8
#define Ec 64
#define ROWSTRIDE (Hc*Ec)

#define LTILE 128
#define STILE 64
#define NTHREADS 256
#define PADH 72                 // smem pitch in halves: 144B -> conflict-free LDSM phases

#define SQ_H (LTILE*PADH)       // 9216 halves
#define SK_H (STILE*PADH)       // 4608
#define SV_H (STILE*PADH)       // 4608
#define SMEM_BYTES ((SQ_H + SK_H + SV_H) * 2)   // 36864 B

// D(16x8,f32) += A(16x16,f16,row) * B(16x8,f16,col)
static __device__ __forceinline__ void mma16(float* c, const uint32_t* a, const uint32_t* b) {
    asm volatile(
        "mma.sync.aligned.m16n8k16.row.col.f32.f16.f16.f32 "
        "{%0,%1,%2,%3}, {%4,%5,%6,%7}, {%8,%9}, {%0,%1,%2,%3};"
        : "+f"(c[0]), "+f"(c[1]), "+f"(c[2]), "+f"(c[3])
        : "r"(a[0]), "r"(a[1]), "r"(a[2]), "r"(a[3]), "r"(b[0]), "r"(b[1]));
}
static __device__ __forceinline__ void ldsm4(uint32_t* r, uint32_t addr) {
    asm volatile("ldmatrix.sync.aligned.m8n8.x4.shared.b16 {%0,%1,%2,%3}, [%4];"
                 : "=r"(r[0]), "=r"(r[1]), "=r"(r[2]), "=r"(r[3]) : "r"(addr));
}
static __device__ __forceinline__ void ldsm4t(uint32_t* r, uint32_t addr) {
    asm volatile("ldmatrix.sync.aligned.m8n8.x4.trans.shared.b16 {%0,%1,%2,%3}, [%4];"
                 : "=r"(r[0]), "=r"(r[1]), "=r"(r[2]), "=r"(r[3]) : "r"(addr));
}
static __device__ __forceinline__ uint2 f4toh4(float4 v, float sc) {
    __half2 lo = __floats2half2_rn(v.x * sc, v.y * sc);
    __half2 hi = __floats2half2_rn(v.z * sc, v.w * sc);
    uint2 u;
    u.x = *(uint32_t*)&lo;  u.y = *(uint32_t*)&hi;
    return u;
}
static __device__ __forceinline__ uint32_t h2bits(float a, float b) {
    __half2 h = __floats2half2_rn(a, b);
    return *(uint32_t*)&h;
}

extern "C" __global__ void __launch_bounds__(NTHREADS, 2)
attn_f16_kernel(const float* __restrict__ Q, const float* __restrict__ K,
                const float* __restrict__ V, float* __restrict__ O)
{
    extern __shared__ __half smem_h[];
    __half* sQ = smem_h;
    __half* sK = sQ + SQ_H;
    __half* sV = sK + SK_H;

    const int tid  = threadIdx.x;
    const int w    = tid >> 5;          // warp 0..7, owns query rows [w*16, w*16+16)
    const int lane = tid & 31;
    const int g    = lane >> 2;         // 0..7
    const int t    = lane & 3;          // 0..3

    const int qt  = blockIdx.x;         // 0..7
    const int bnh = blockIdx.y;         // 0..127
    const int h   = bnh & (Hc - 1);
    const int bn  = bnh >> 3;
    const size_t base = (size_t)bn * Lc * ROWSTRIDE + (size_t)h * Ec;
    const int q0 = qt * LTILE;

    const int lr = tid >> 4;            // 0..15 (fill row)
    const int le = (tid & 15) << 2;     // 0,4,..,60 (fill col, halves)

    // ---- Q tile -> smem as f16, pre-scaled by 1/sqrt(E) ----
    #pragma unroll
    for (int it = 0; it < LTILE / 16; ++it) {
        int r = it * 16 + lr;
        float4 v = *(const float4*)(Q + base + (size_t)(q0 + r) * ROWSTRIDE + le);
        *(uint2*)(&sQ[r * PADH + le]) = f4toh4(v, 0.125f);
    }

    // ---- per-lane ldmatrix base addresses ----
    const int rw  = w * 16;
    const int la7 = lane & 7;
    const int lb  = (lane >> 3) & 1;
    const int lc  = lane >> 4;
    const uint32_t qb = (uint32_t)__cvta_generic_to_shared(sQ);
    const uint32_t kb = (uint32_t)__cvta_generic_to_shared(sK);
    const uint32_t vb = (uint32_t)__cvta_generic_to_shared(sV);
    // Q A-frag: row = rw + la7 + 8*lb, col = 8*lc (+16*kk)
    const uint32_t q_ls = qb + (uint32_t)(((rw + la7 + 8 * lb) * PADH + 8 * lc) * 2);
    // K B-frag: row = la7 + 8*lc (+16*np), col = 8*lb (+16*kk)
    const uint32_t k_ls = kb + (uint32_t)(((la7 + 8 * lc) * PADH + 8 * lb) * 2);
    // V B-frag (trans): row = la7 + 8*lb (+16*kk), col = 8*lc (+16*np)
    const uint32_t v_ls = vb + (uint32_t)(((la7 + 8 * lb) * PADH + 8 * lc) * 2);

    float o[8][4];
    #pragma unroll
    for (int nt = 0; nt < 8; ++nt) { o[nt][0]=0.f; o[nt][1]=0.f; o[nt][2]=0.f; o[nt][3]=0.f; }
    float m0 = -INFINITY, m1 = -INFINITY, l0 = 0.f, l1 = 0.f;

    const int r0g = q0 + rw + g;        // global query row (row-set 1 = +8)
    const int nkt = 2 * qt + 2;         // causal: key tiles 0 .. 2qt+1

    for (int kt = 0; kt < nkt; ++kt) {
        const int k0 = kt * STILE;

        __syncthreads();                // previous iteration done reading sK/sV
        #pragma unroll
        for (int it = 0; it < STILE / 16; ++it) {
            int r = it * 16 + lr;
            size_t ga = base + (size_t)(k0 + r) * ROWSTRIDE + le;
            *(uint2*)(&sK[r * PADH + le]) = f4toh4(*(const float4*)(K + ga), 1.0f);
            *(uint2*)(&sV[r * PADH + le]) = f4toh4(*(const float4*)(V + ga), 1.0f);
        }
        __syncthreads();

        // Warp entirely above the diagonal for this key tile -> nothing to do.
        if (k0 > q0 + rw + 15) continue;

        // ---- GEMM1: S(16x64) = Q_w(16x64) * K^T, 4 k16-chunks ----
        float s[8][4];
        #pragma unroll
        for (int nt = 0; nt < 8; ++nt) { s[nt][0]=0.f; s[nt][1]=0.f; s[nt][2]=0.f; s[nt][3]=0.f; }

        #pragma unroll
        for (int kk = 0; kk < 4; ++kk) {
            uint32_t a[4]; ldsm4(a, q_ls + kk * 32);
            #pragma unroll
            for (int np = 0; np < 4; ++np) {
                uint32_t b[4]; ldsm4(b, k_ls + (uint32_t)(np * 16 * PADH * 2 + kk * 32));
                mma16(s[2*np],     a, b);
                mma16(s[2*np + 1], a, b + 2);
            }
        }

        // ---- causal mask (S pre-scaled via Q) ----
        if (k0 + STILE - 1 > q0 + rw) {
            #pragma unroll
            for (int nt = 0; nt < 8; ++nt) {
                int c = k0 + nt * 8 + 2 * t;
                if (c     > r0g)     s[nt][0] = -INFINITY;
                if (c + 1 > r0g)     s[nt][1] = -INFINITY;
                if (c     > r0g + 8) s[nt][2] = -INFINITY;
                if (c + 1 > r0g + 8) s[nt][3] = -INFINITY;
            }
        }

        // ---- online softmax; each output row lives on 4 lanes (same g) ----
        float mx0 = -INFINITY, mx1 = -INFINITY;
        #pragma unroll
        for (int nt = 0; nt < 8; ++nt) {
            mx0 = fmaxf(mx0, fmaxf(s[nt][0], s[nt][1]));
            mx1 = fmaxf(mx1, fmaxf(s[nt][2], s[nt][3]));
        }
        mx0 = fmaxf(mx0, __shfl_xor_sync(0xffffffffu, mx0, 1));
        mx0 = fmaxf(mx0, __shfl_xor_sync(0xffffffffu, mx0, 2));
        mx1 = fmaxf(mx1, __shfl_xor_sync(0xffffffffu, mx1, 1));
        mx1 = fmaxf(mx1, __shfl_xor_sync(0xffffffffu, mx1, 2));

        float mn0 = fmaxf(m0, mx0), mn1 = fmaxf(m1, mx1);
        float cr0 = __expf(m0 - mn0), cr1 = __expf(m1 - mn1);

        float ps0 = 0.f, ps1 = 0.f;
        #pragma unroll
        for (int nt = 0; nt < 8; ++nt) {
            s[nt][0] = __expf(s[nt][0] - mn0);
            s[nt][1] = __expf(s[nt][1] - mn0);
            s[nt][2] = __expf(s[nt][2] - mn1);
            s[nt][3] = __expf(s[nt][3] - mn1);
            ps0 += s[nt][0] + s[nt][1];
            ps1 += s[nt][2] + s[nt][3];
        }
        ps0 += __shfl_xor_sync(0xffffffffu, ps0, 1);
        ps0 += __shfl_xor_sync(0xffffffffu, ps0, 2);
        ps1 += __shfl_xor_sync(0xffffffffu, ps1, 1);
        ps1 += __shfl_xor_sync(0xffffffffu, ps1, 2);

        l0 = l0 * cr0 + ps0;  l1 = l1 * cr1 + ps1;
        m0 = mn0;             m1 = mn1;
        #pragma unroll
        for (int nt = 0; nt < 8; ++nt) {
            o[nt][0] *= cr0; o[nt][1] *= cr0; o[nt][2] *= cr1; o[nt][3] *= cr1;
        }

        // ---- GEMM2: O(16x64) += P(16x64) * V(64x64) ----
        // A-frag comes straight from the GEMM1 C-frags: C(m16n8) pair layout
        // {C[g][2t],C[g][2t+1],C[g+8][2t],C[g+8][2t+1]} == A(m16n8k16) per 16-col chunk.
        #pragma unroll
        for (int kk = 0; kk < 4; ++kk) {
            uint32_t a[4];
            a[0] = h2bits(s[2*kk][0],     s[2*kk][1]);       // P[g   ][16kk + 2t..]
            a[1] = h2bits(s[2*kk][2],     s[2*kk][3]);       // P[g+8 ][16kk + 2t..]
            a[2] = h2bits(s[2*kk + 1][0], s[2*kk + 1][1]);   // P[g   ][16kk+8+2t..]
            a[3] = h2bits(s[2*kk + 1][2], s[2*kk + 1][3]);   // P[g+8 ][16kk+8+2t..]
            #pragma unroll
            for (int np = 0; np < 4; ++np) {
                uint32_t b[4];
                ldsm4t(b, v_ls + (uint32_t)(kk * 16 * PADH * 2 + np * 32));
                mma16(o[2*np],     a, b);
                mma16(o[2*np + 1], a, b + 2);
            }
        }
    }

    // ---- epilogue: normalize, store ----
    const float inv0 = 1.f / l0, inv1 = 1.f / l1;
    const size_t ro0 = base + (size_t)r0g * ROWSTRIDE;
    const size_t ro1 = ro0 + (size_t)8 * ROWSTRIDE;
    #pragma unroll
    for (int nt = 0; nt < 8; ++nt) {
        float2 v0; v0.x = o[nt][0] * inv0; v0.y = o[nt][1] * inv0;
        float2 v1; v1.x = o[nt][2] * inv1; v1.y = o[nt][3] * inv1;
        *(float2*)(O + ro0 + nt * 8 + 2 * t) = v0;
        *(float2*)(O + ro1 + nt * 8 + 2 * t) = v1;
    }
}

extern "C" void kernel_launch(void* const* d_in, const int* in_sizes, int n_in,
                              void* d_out, int out_size)
{
    const float* Q = (const float*)d_in[0];
    const float* K = (const float*)d_in[1];
    const float* V = (const float*)d_in[2];
    float* O = (float*)d_out;

    cudaFuncSetAttribute(attn_f16_kernel,
                         cudaFuncAttributeMaxDynamicSharedMemorySize, SMEM_BYTES);

    dim3 grid(Lc / LTILE, Bc * Nc * Hc);    // (8, 128)
    attn_f16_kernel<<<grid, NTHREADS, SMEM_BYTES>>>(Q, K, V, O);
}

// round 9
// speedup vs baseline: 2.1904x; 1.0663x over previous
#include <cuda_runtime.h>
#include <cuda_fp16.h>
#include <math.h>
#include <stdint.h>

// [B,N,L,H,E] = [4,4,1024,8,64] fp32. For fixed (b,n,h): row l at bn*L*H*E + l*H*E + h*E,
// contiguous E=64 floats, stride H*E=512 floats between consecutive l.

#define Bc 4
#define Nc 4
#define Lc 1024
#define Hc 8
#define Ec 64
#define ROWSTRIDE (Hc*Ec)

#define LTILE 128
#define STILE 64
#define NTHREADS 128            // 4 warps, each owns 32 query rows (2 rowsets of 16)
#define PADH 72                 // smem pitch in halves: 144B -> conflict-free LDSM phases

#define SQ_H (LTILE*PADH)       // 9216 halves
#define SK_H (STILE*PADH)       // 4608
#define SV_H (STILE*PADH)       // 4608
#define SMEM_BYTES ((SQ_H + SK_H + SV_H) * 2)   // 36864 B -> 3 CTAs/SM

// Q pre-scale: (1/sqrt(64)) * log2(e)  -> softmax in exp2 domain
#define QSCALE 0.18033688011111204f

// D(16x8,f32) += A(16x16,f16,row) * B(16x8,f16,col)
static __device__ __forceinline__ void mma16(float* c, const uint32_t* a, const uint32_t* b) {
    asm volatile(
        "mma.sync.aligned.m16n8k16.row.col.f32.f16.f16.f32 "
        "{%0,%1,%2,%3}, {%4,%5,%6,%7}, {%8,%9}, {%0,%1,%2,%3};"
        : "+f"(c[0]), "+f"(c[1]), "+f"(c[2]), "+f"(c[3])
        : "r"(a[0]), "r"(a[1]), "r"(a[2]), "r"(a[3]), "r"(b[0]), "r"(b[1]));
}
static __device__ __forceinline__ void ldsm4(uint32_t* r, uint32_t addr) {
    asm volatile("ldmatrix.sync.aligned.m8n8.x4.shared.b16 {%0,%1,%2,%3}, [%4];"
                 : "=r"(r[0]), "=r"(r[1]), "=r"(r[2]), "=r"(r[3]) : "r"(addr));
}
static __device__ __forceinline__ void ldsm4t(uint32_t* r, uint32_t addr) {
    asm volatile("ldmatrix.sync.aligned.m8n8.x4.trans.shared.b16 {%0,%1,%2,%3}, [%4];"
                 : "=r"(r[0]), "=r"(r[1]), "=r"(r[2]), "=r"(r[3]) : "r"(addr));
}
static __device__ __forceinline__ float ex2(float x) {
    float y; asm("ex2.approx.f32 %0, %1;" : "=f"(y) : "f"(x)); return y;
}
static __device__ __forceinline__ uint2 f4toh4(float4 v, float sc) {
    __half2 lo = __floats2half2_rn(v.x * sc, v.y * sc);
    __half2 hi = __floats2half2_rn(v.z * sc, v.w * sc);
    uint2 u;
    u.x = *(uint32_t*)&lo;  u.y = *(uint32_t*)&hi;
    return u;
}
static __device__ __forceinline__ uint32_t h2bits(float a, float b) {
    __half2 h = __floats2half2_rn(a, b);
    return *(uint32_t*)&h;
}

// online-softmax update for one 16-row rowset held as C-frags s[8][4]
static __device__ __forceinline__ void softmax_update(
    float s[8][4], float& m0, float& m1, float& l0, float& l1, float o[8][4])
{
    float mx0 = -INFINITY, mx1 = -INFINITY;
    #pragma unroll
    for (int nt = 0; nt < 8; ++nt) {
        mx0 = fmaxf(mx0, fmaxf(s[nt][0], s[nt][1]));
        mx1 = fmaxf(mx1, fmaxf(s[nt][2], s[nt][3]));
    }
    mx0 = fmaxf(mx0, __shfl_xor_sync(0xffffffffu, mx0, 1));
    mx0 = fmaxf(mx0, __shfl_xor_sync(0xffffffffu, mx0, 2));
    mx1 = fmaxf(mx1, __shfl_xor_sync(0xffffffffu, mx1, 1));
    mx1 = fmaxf(mx1, __shfl_xor_sync(0xffffffffu, mx1, 2));

    float mn0 = fmaxf(m0, mx0), mn1 = fmaxf(m1, mx1);
    float cr0 = ex2(m0 - mn0),  cr1 = ex2(m1 - mn1);

    float ps0 = 0.f, ps1 = 0.f;
    #pragma unroll
    for (int nt = 0; nt < 8; ++nt) {
        s[nt][0] = ex2(s[nt][0] - mn0);
        s[nt][1] = ex2(s[nt][1] - mn0);
        s[nt][2] = ex2(s[nt][2] - mn1);
        s[nt][3] = ex2(s[nt][3] - mn1);
        ps0 += s[nt][0] + s[nt][1];
        ps1 += s[nt][2] + s[nt][3];
    }
    ps0 += __shfl_xor_sync(0xffffffffu, ps0, 1);
    ps0 += __shfl_xor_sync(0xffffffffu, ps0, 2);
    ps1 += __shfl_xor_sync(0xffffffffu, ps1, 1);
    ps1 += __shfl_xor_sync(0xffffffffu, ps1, 2);

    l0 = l0 * cr0 + ps0;  l1 = l1 * cr1 + ps1;
    m0 = mn0;             m1 = mn1;
    #pragma unroll
    for (int nt = 0; nt < 8; ++nt) {
        o[nt][0] *= cr0; o[nt][1] *= cr0; o[nt][2] *= cr1; o[nt][3] *= cr1;
    }
}

extern "C" __global__ void __launch_bounds__(NTHREADS, 3)
attn_f16w32_kernel(const float* __restrict__ Q, const float* __restrict__ K,
                   const float* __restrict__ V, float* __restrict__ O)
{
    extern __shared__ __half smem_h[];
    __half* sQ = smem_h;
    __half* sK = sQ + SQ_H;
    __half* sV = sK + SK_H;

    const int tid  = threadIdx.x;
    const int w    = tid >> 5;          // warp 0..3, owns query rows [w*32, w*32+32)
    const int lane = tid & 31;
    const int g    = lane >> 2;         // 0..7
    const int t    = lane & 3;          // 0..3

    const int qt  = blockIdx.x;         // 0..7
    const int bnh = blockIdx.y;         // 0..127
    const int h   = bnh & (Hc - 1);
    const int bn  = bnh >> 3;
    const size_t base = (size_t)bn * Lc * ROWSTRIDE + (size_t)h * Ec;
    const int q0 = qt * LTILE;

    const int lr = tid >> 4;            // 0..7 (fill row)
    const int le = (tid & 15) << 2;     // 0,4,..,60 (fill col, halves)

    // ---- Q tile -> smem as f16, pre-scaled by 1/sqrt(E)*log2(e) ----
    #pragma unroll
    for (int it = 0; it < LTILE / 8; ++it) {
        int r = it * 8 + lr;
        float4 v = *(const float4*)(Q + base + (size_t)(q0 + r) * ROWSTRIDE + le);
        *(uint2*)(&sQ[r * PADH + le]) = f4toh4(v, QSCALE);
    }

    // ---- per-lane ldmatrix base addresses ----
    const int rw  = w * 32;
    const int la7 = lane & 7;
    const int lb  = (lane >> 3) & 1;
    const int lc  = lane >> 4;
    const uint32_t qb = (uint32_t)__cvta_generic_to_shared(sQ);
    const uint32_t kb = (uint32_t)__cvta_generic_to_shared(sK);
    const uint32_t vb = (uint32_t)__cvta_generic_to_shared(sV);
    // Q A-frags for rowsets 0/1: row = rw + 16*rs + la7 + 8*lb, col = 8*lc (+16*kk)
    const uint32_t q_ls0 = qb + (uint32_t)(((rw +      la7 + 8 * lb) * PADH + 8 * lc) * 2);
    const uint32_t q_ls1 = qb + (uint32_t)(((rw + 16 + la7 + 8 * lb) * PADH + 8 * lc) * 2);
    // K B-frag: row = la7 + 8*lc (+16*np), col = 8*lb (+16*kk)
    const uint32_t k_ls = kb + (uint32_t)(((la7 + 8 * lc) * PADH + 8 * lb) * 2);
    // V B-frag (trans): row = la7 + 8*lb (+16*kk), col = 8*lc (+16*np)
    const uint32_t v_ls = vb + (uint32_t)(((la7 + 8 * lb) * PADH + 8 * lc) * 2);

    float o0[8][4], o1[8][4];
    #pragma unroll
    for (int nt = 0; nt < 8; ++nt) {
        o0[nt][0]=0.f; o0[nt][1]=0.f; o0[nt][2]=0.f; o0[nt][3]=0.f;
        o1[nt][0]=0.f; o1[nt][1]=0.f; o1[nt][2]=0.f; o1[nt][3]=0.f;
    }
    float m00 = -INFINITY, m01 = -INFINITY, m10 = -INFINITY, m11 = -INFINITY;
    float l00 = 0.f, l01 = 0.f, l10 = 0.f, l11 = 0.f;

    const int r0a = q0 + rw + g;        // rowset0 groups: r0a, r0a+8
    const int r0b = r0a + 16;           // rowset1 groups: r0b, r0b+8
    const int nkt = 2 * qt + 2;         // causal: key tiles 0 .. 2qt+1

    for (int kt = 0; kt < nkt; ++kt) {
        const int k0 = kt * STILE;

        __syncthreads();                // previous iteration done reading sK/sV
        #pragma unroll
        for (int it = 0; it < STILE / 8; ++it) {
            int r = it * 8 + lr;
            size_t ga = base + (size_t)(k0 + r) * ROWSTRIDE + le;
            *(uint2*)(&sK[r * PADH + le]) = f4toh4(*(const float4*)(K + ga), 1.0f);
            *(uint2*)(&sV[r * PADH + le]) = f4toh4(*(const float4*)(V + ga), 1.0f);
        }
        __syncthreads();

        // Warp entirely above the diagonal for this key tile -> nothing to do.
        if (k0 > q0 + rw + 31) continue;

        // ---- GEMM1: S(32x64) = Q_w(32x64) * K^T, 4 k16-chunks, shared K frags ----
        float s0[8][4], s1[8][4];
        #pragma unroll
        for (int nt = 0; nt < 8; ++nt) {
            s0[nt][0]=0.f; s0[nt][1]=0.f; s0[nt][2]=0.f; s0[nt][3]=0.f;
            s1[nt][0]=0.f; s1[nt][1]=0.f; s1[nt][2]=0.f; s1[nt][3]=0.f;
        }
        #pragma unroll
        for (int kk = 0; kk < 4; ++kk) {
            uint32_t a0[4], a1[4];
            ldsm4(a0, q_ls0 + kk * 32);
            ldsm4(a1, q_ls1 + kk * 32);
            #pragma unroll
            for (int np = 0; np < 4; ++np) {
                uint32_t b[4]; ldsm4(b, k_ls + (uint32_t)(np * 16 * PADH * 2 + kk * 32));
                mma16(s0[2*np],     a0, b);
                mma16(s0[2*np + 1], a0, b + 2);
                mma16(s1[2*np],     a1, b);
                mma16(s1[2*np + 1], a1, b + 2);
            }
        }

        // ---- causal mask (S pre-scaled via Q) ----
        if (k0 + STILE - 1 > q0 + rw) {
            #pragma unroll
            for (int nt = 0; nt < 8; ++nt) {
                int c = k0 + nt * 8 + 2 * t;
                if (c     > r0a)     s0[nt][0] = -INFINITY;
                if (c + 1 > r0a)     s0[nt][1] = -INFINITY;
                if (c     > r0a + 8) s0[nt][2] = -INFINITY;
                if (c + 1 > r0a + 8) s0[nt][3] = -INFINITY;
                if (c     > r0b)     s1[nt][0] = -INFINITY;
                if (c + 1 > r0b)     s1[nt][1] = -INFINITY;
                if (c     > r0b + 8) s1[nt][2] = -INFINITY;
                if (c + 1 > r0b + 8) s1[nt][3] = -INFINITY;
            }
        }

        // ---- online softmax per rowset (exp2 domain) ----
        softmax_update(s0, m00, m01, l00, l01, o0);
        softmax_update(s1, m10, m11, l10, l11, o1);

        // ---- GEMM2: O(32x64) += P(32x64) * V(64x64); A-frags from C-frags, shared V frags ----
        #pragma unroll
        for (int kk = 0; kk < 4; ++kk) {
            uint32_t a0[4], a1[4];
            a0[0] = h2bits(s0[2*kk][0],     s0[2*kk][1]);
            a0[1] = h2bits(s0[2*kk][2],     s0[2*kk][3]);
            a0[2] = h2bits(s0[2*kk + 1][0], s0[2*kk + 1][1]);
            a0[3] = h2bits(s0[2*kk + 1][2], s0[2*kk + 1][3]);
            a1[0] = h2bits(s1[2*kk][0],     s1[2*kk][1]);
            a1[1] = h2bits(s1[2*kk][2],     s1[2*kk][3]);
            a1[2] = h2bits(s1[2*kk + 1][0], s1[2*kk + 1][1]);
            a1[3] = h2bits(s1[2*kk + 1][2], s1[2*kk + 1][3]);
            #pragma unroll
            for (int np = 0; np < 4; ++np) {
                uint32_t b[4];
                ldsm4t(b, v_ls + (uint32_t)(kk * 16 * PADH * 2 + np * 32));
                mma16(o0[2*np],     a0, b);
                mma16(o0[2*np + 1], a0, b + 2);
                mma16(o1[2*np],     a1, b);
                mma16(o1[2*np + 1], a1, b + 2);
            }
        }
    }

    // ---- epilogue: normalize, store 32 rows/warp ----
    const float i00 = 1.f / l00, i01 = 1.f / l01, i10 = 1.f / l10, i11 = 1.f / l11;
    const size_t ra0 = base + (size_t)r0a * ROWSTRIDE;
    const size_t ra1 = ra0 + (size_t)8 * ROWSTRIDE;
    const size_t rb0 = base + (size_t)r0b * ROWSTRIDE;
    const size_t rb1 = rb0 + (size_t)8 * ROWSTRIDE;
    #pragma unroll
    for (int nt = 0; nt < 8; ++nt) {
        float2 v;
        v.x = o0[nt][0] * i00; v.y = o0[nt][1] * i00; *(float2*)(O + ra0 + nt*8 + 2*t) = v;
        v.x = o0[nt][2] * i01; v.y = o0[nt][3] * i01; *(float2*)(O + ra1 + nt*8 + 2*t) = v;
        v.x = o1[nt][0] * i10; v.y = o1[nt][1] * i10; *(float2*)(O + rb0 + nt*8 + 2*t) = v;
        v.x = o1[nt][2] * i11; v.y = o1[nt][3] * i11; *(float2*)(O + rb1 + nt*8 + 2*t) = v;
    }
}

extern "C" void kernel_launch(void* const* d_in, const int* in_sizes, int n_in,
                              void* d_out, int out_size)
{
    const float* Q = (const float*)d_in[0];
    const float* K = (const float*)d_in[1];
    const float* V = (const float*)d_in[2];
    float* O = (float*)d_out;

    cudaFuncSetAttribute(attn_f16w32_kernel,
                         cudaFuncAttributeMaxDynamicSharedMemorySize, SMEM_BYTES);

    dim3 grid(Lc / LTILE, Bc * Nc * Hc);    // (8, 128)
    attn_f16w32_kernel<<<grid, NTHREADS, SMEM_BYTES>>>(Q, K, V, O);
}

// round 10
// speedup vs baseline: 2.3982x; 1.0949x over previous
#include <cuda_runtime.h>
#include <cuda_fp16.h>
#include <math.h>
#include <stdint.h>

// [B,N,L,H,E] = [4,4,1024,8,64] fp32. For fixed (b,n,h): row l at bn*L*H*E + l*H*E + h*E,
// contiguous E=64 floats, stride H*E=512 floats between consecutive l.

#define Bc 4
#define Nc 4
#define Lc 1024
#define Hc 8
#define Ec 64
#define ROWSTRIDE (Hc*Ec)

#define LTILE 128
#define STILE 64
#define NTHREADS 128            // 4 warps, each owns 32 query rows (2 rowsets of 16)
#define PADH 72                 // smem pitch in halves: 144B -> conflict-free LDSM phases

#define SQ_H (LTILE*PADH)       // 9216 halves
#define SK_H (STILE*PADH)       // 4608
#define SV_H (STILE*PADH)       // 4608
#define SMEM_BYTES ((SQ_H + SK_H + SV_H) * 2)   // 36864 B -> 3 CTAs/SM

// Q pre-scale: (1/sqrt(64)) * log2(e)  -> softmax in exp2 domain
#define QSCALE 0.18033688011111204f

// D(16x8,f32) += A(16x16,f16,row) * B(16x8,f16,col)
static __device__ __forceinline__ void mma16(float* c, const uint32_t* a, const uint32_t* b) {
    asm volatile(
        "mma.sync.aligned.m16n8k16.row.col.f32.f16.f16.f32 "
        "{%0,%1,%2,%3}, {%4,%5,%6,%7}, {%8,%9}, {%0,%1,%2,%3};"
        : "+f"(c[0]), "+f"(c[1]), "+f"(c[2]), "+f"(c[3])
        : "r"(a[0]), "r"(a[1]), "r"(a[2]), "r"(a[3]), "r"(b[0]), "r"(b[1]));
}
static __device__ __forceinline__ void ldsm4(uint32_t* r, uint32_t addr) {
    asm volatile("ldmatrix.sync.aligned.m8n8.x4.shared.b16 {%0,%1,%2,%3}, [%4];"
                 : "=r"(r[0]), "=r"(r[1]), "=r"(r[2]), "=r"(r[3]) : "r"(addr));
}
static __device__ __forceinline__ void ldsm4t(uint32_t* r, uint32_t addr) {
    asm volatile("ldmatrix.sync.aligned.m8n8.x4.trans.shared.b16 {%0,%1,%2,%3}, [%4];"
                 : "=r"(r[0]), "=r"(r[1]), "=r"(r[2]), "=r"(r[3]) : "r"(addr));
}
static __device__ __forceinline__ float ex2(float x) {
    float y; asm("ex2.approx.f32 %0, %1;" : "=f"(y) : "f"(x)); return y;
}
static __device__ __forceinline__ uint32_t ex2h2(uint32_t x) {
    uint32_t y; asm("ex2.approx.f16x2 %0, %1;" : "=r"(y) : "r"(x)); return y;
}
static __device__ __forceinline__ uint32_t f2h2(float a, float b) {
    __half2 h = __floats2half2_rn(a, b);
    return *(uint32_t*)&h;
}
static __device__ __forceinline__ uint2 f4toh4(float4 v, float sc) {
    __half2 lo = __floats2half2_rn(v.x * sc, v.y * sc);
    __half2 hi = __floats2half2_rn(v.z * sc, v.w * sc);
    uint2 u;
    u.x = *(uint32_t*)&lo;  u.y = *(uint32_t*)&hi;
    return u;
}

// Online-softmax for one 16-row rowset: consumes f32 C-frags s[8][4], produces
// GEMM2 A-frags af[8][2] (f16x2, via ex2.approx.f16x2), updates m/l, rescales o.
// Row sums come from an extra tensor-core mma against ones (exact f32 sum of the
// same f16 p values GEMM2 consumes) -- no shuffle, no scalar adds.
static __device__ __forceinline__ void softmax_frag(
    float s[8][4], float& m0, float& m1, float& l0, float& l1,
    float o[8][4], uint32_t af[8][2])
{
    float mx0 = -INFINITY, mx1 = -INFINITY;
    #pragma unroll
    for (int nt = 0; nt < 8; ++nt) {
        mx0 = fmaxf(mx0, fmaxf(s[nt][0], s[nt][1]));
        mx1 = fmaxf(mx1, fmaxf(s[nt][2], s[nt][3]));
    }
    mx0 = fmaxf(mx0, __shfl_xor_sync(0xffffffffu, mx0, 1));
    mx0 = fmaxf(mx0, __shfl_xor_sync(0xffffffffu, mx0, 2));
    mx1 = fmaxf(mx1, __shfl_xor_sync(0xffffffffu, mx1, 1));
    mx1 = fmaxf(mx1, __shfl_xor_sync(0xffffffffu, mx1, 2));

    float mn0 = fmaxf(m0, mx0), mn1 = fmaxf(m1, mx1);
    float cr0 = ex2(m0 - mn0),  cr1 = ex2(m1 - mn1);

    // p = exp2(s - mn) computed directly in f16x2 -> these ARE the A-frag words
    #pragma unroll
    for (int nt = 0; nt < 8; ++nt) {
        af[nt][0] = ex2h2(f2h2(s[nt][0] - mn0, s[nt][1] - mn0));   // rows g,  masked -inf -> 0
        af[nt][1] = ex2h2(f2h2(s[nt][2] - mn1, s[nt][3] - mn1));   // rows g+8
    }

    // row sums l' = P * ones(16x8): C[0]=row g sum, C[2]=row g+8 sum (all lanes)
    float ls[4] = {0.f, 0.f, 0.f, 0.f};
    const uint32_t one2[2] = {0x3C003C00u, 0x3C003C00u};
    #pragma unroll
    for (int kk = 0; kk < 4; ++kk) {
        uint32_t a[4] = { af[2*kk][0], af[2*kk][1], af[2*kk+1][0], af[2*kk+1][1] };
        mma16(ls, a, one2);
    }

    l0 = l0 * cr0 + ls[0];
    l1 = l1 * cr1 + ls[2];
    m0 = mn0;  m1 = mn1;

    if (__ballot_sync(0xffffffffu, (cr0 != 1.f) | (cr1 != 1.f))) {
        #pragma unroll
        for (int nt = 0; nt < 8; ++nt) {
            o[nt][0] *= cr0; o[nt][1] *= cr0; o[nt][2] *= cr1; o[nt][3] *= cr1;
        }
    }
}

extern "C" __global__ void __launch_bounds__(NTHREADS, 3)
attn_f16x_kernel(const float* __restrict__ Q, const float* __restrict__ K,
                 const float* __restrict__ V, float* __restrict__ O)
{
    extern __shared__ __half smem_h[];
    __half* sQ = smem_h;
    __half* sK = sQ + SQ_H;
    __half* sV = sK + SK_H;

    const int tid  = threadIdx.x;
    const int w    = tid >> 5;          // warp 0..3, owns query rows [w*32, w*32+32)
    const int lane = tid & 31;
    const int g    = lane >> 2;         // 0..7
    const int t    = lane & 3;          // 0..3

    const int qt  = blockIdx.x;         // 0..7
    const int bnh = blockIdx.y;         // 0..127
    const int h   = bnh & (Hc - 1);
    const int bn  = bnh >> 3;
    const size_t base = (size_t)bn * Lc * ROWSTRIDE + (size_t)h * Ec;
    const int q0 = qt * LTILE;

    const int lr = tid >> 4;            // 0..7 (fill row)
    const int le = (tid & 15) << 2;     // 0,4,..,60 (fill col, halves)

    // ---- Q tile -> smem as f16, pre-scaled by 1/sqrt(E)*log2(e) ----
    #pragma unroll
    for (int it = 0; it < LTILE / 8; ++it) {
        int r = it * 8 + lr;
        float4 v = *(const float4*)(Q + base + (size_t)(q0 + r) * ROWSTRIDE + le);
        *(uint2*)(&sQ[r * PADH + le]) = f4toh4(v, QSCALE);
    }

    // ---- per-lane ldmatrix base addresses ----
    const int rw  = w * 32;
    const int la7 = lane & 7;
    const int lb  = (lane >> 3) & 1;
    const int lc  = lane >> 4;
    const uint32_t qb = (uint32_t)__cvta_generic_to_shared(sQ);
    const uint32_t kb = (uint32_t)__cvta_generic_to_shared(sK);
    const uint32_t vb = (uint32_t)__cvta_generic_to_shared(sV);
    const uint32_t q_ls0 = qb + (uint32_t)(((rw +      la7 + 8 * lb) * PADH + 8 * lc) * 2);
    const uint32_t q_ls1 = qb + (uint32_t)(((rw + 16 + la7 + 8 * lb) * PADH + 8 * lc) * 2);
    const uint32_t k_ls = kb + (uint32_t)(((la7 + 8 * lc) * PADH + 8 * lb) * 2);
    const uint32_t v_ls = vb + (uint32_t)(((la7 + 8 * lb) * PADH + 8 * lc) * 2);

    float o0[8][4], o1[8][4];
    #pragma unroll
    for (int nt = 0; nt < 8; ++nt) {
        o0[nt][0]=0.f; o0[nt][1]=0.f; o0[nt][2]=0.f; o0[nt][3]=0.f;
        o1[nt][0]=0.f; o1[nt][1]=0.f; o1[nt][2]=0.f; o1[nt][3]=0.f;
    }
    float m00 = -INFINITY, m01 = -INFINITY, m10 = -INFINITY, m11 = -INFINITY;
    float l00 = 0.f, l01 = 0.f, l10 = 0.f, l11 = 0.f;

    const int r0a = q0 + rw + g;        // rowset0 groups: r0a, r0a+8
    const int r0b = r0a + 16;           // rowset1 groups: r0b, r0b+8
    const int nkt = 2 * qt + 2;         // causal: key tiles 0 .. 2qt+1

    for (int kt = 0; kt < nkt; ++kt) {
        const int k0 = kt * STILE;

        __syncthreads();                // previous iteration done reading sK/sV
        #pragma unroll
        for (int it = 0; it < STILE / 8; ++it) {
            int r = it * 8 + lr;
            size_t ga = base + (size_t)(k0 + r) * ROWSTRIDE + le;
            *(uint2*)(&sK[r * PADH + le]) = f4toh4(*(const float4*)(K + ga), 1.0f);
            *(uint2*)(&sV[r * PADH + le]) = f4toh4(*(const float4*)(V + ga), 1.0f);
        }
        __syncthreads();

        // Warp entirely above the diagonal for this key tile -> nothing to do.
        if (k0 > q0 + rw + 31) continue;

        // ---- GEMM1: S(32x64) = Q_w(32x64) * K^T, 4 k16-chunks, shared K frags ----
        float s0[8][4], s1[8][4];
        #pragma unroll
        for (int nt = 0; nt < 8; ++nt) {
            s0[nt][0]=0.f; s0[nt][1]=0.f; s0[nt][2]=0.f; s0[nt][3]=0.f;
            s1[nt][0]=0.f; s1[nt][1]=0.f; s1[nt][2]=0.f; s1[nt][3]=0.f;
        }
        #pragma unroll
        for (int kk = 0; kk < 4; ++kk) {
            uint32_t a0[4], a1[4];
            ldsm4(a0, q_ls0 + kk * 32);
            ldsm4(a1, q_ls1 + kk * 32);
            #pragma unroll
            for (int np = 0; np < 4; ++np) {
                uint32_t b[4]; ldsm4(b, k_ls + (uint32_t)(np * 16 * PADH * 2 + kk * 32));
                mma16(s0[2*np],     a0, b);
                mma16(s0[2*np + 1], a0, b + 2);
                mma16(s1[2*np],     a1, b);
                mma16(s1[2*np + 1], a1, b + 2);
            }
        }

        // ---- causal mask (S pre-scaled via Q) ----
        if (k0 + STILE - 1 > q0 + rw) {
            #pragma unroll
            for (int nt = 0; nt < 8; ++nt) {
                int c = k0 + nt * 8 + 2 * t;
                if (c     > r0a)     s0[nt][0] = -INFINITY;
                if (c + 1 > r0a)     s0[nt][1] = -INFINITY;
                if (c     > r0a + 8) s0[nt][2] = -INFINITY;
                if (c + 1 > r0a + 8) s0[nt][3] = -INFINITY;
                if (c     > r0b)     s1[nt][0] = -INFINITY;
                if (c + 1 > r0b)     s1[nt][1] = -INFINITY;
                if (c     > r0b + 8) s1[nt][2] = -INFINITY;
                if (c + 1 > r0b + 8) s1[nt][3] = -INFINITY;
            }
        }

        // ---- online softmax per rowset: emits f16x2 A-frags + tensor-core row sums ----
        uint32_t af0[8][2], af1[8][2];
        softmax_frag(s0, m00, m01, l00, l01, o0, af0);
        softmax_frag(s1, m10, m11, l10, l11, o1, af1);

        // ---- GEMM2: O(32x64) += P(32x64) * V(64x64); A-frags ready, shared V frags ----
        #pragma unroll
        for (int kk = 0; kk < 4; ++kk) {
            uint32_t a0[4] = { af0[2*kk][0], af0[2*kk][1], af0[2*kk+1][0], af0[2*kk+1][1] };
            uint32_t a1[4] = { af1[2*kk][0], af1[2*kk][1], af1[2*kk+1][0], af1[2*kk+1][1] };
            #pragma unroll
            for (int np = 0; np < 4; ++np) {
                uint32_t b[4];
                ldsm4t(b, v_ls + (uint32_t)(kk * 16 * PADH * 2 + np * 32));
                mma16(o0[2*np],     a0, b);
                mma16(o0[2*np + 1], a0, b + 2);
                mma16(o1[2*np],     a1, b);
                mma16(o1[2*np + 1], a1, b + 2);
            }
        }
    }

    // ---- epilogue: normalize, store 32 rows/warp ----
    const float i00 = 1.f / l00, i01 = 1.f / l01, i10 = 1.f / l10, i11 = 1.f / l11;
    const size_t ra0 = base + (size_t)r0a * ROWSTRIDE;
    const size_t ra1 = ra0 + (size_t)8 * ROWSTRIDE;
    const size_t rb0 = base + (size_t)r0b * ROWSTRIDE;
    const size_t rb1 = rb0 + (size_t)8 * ROWSTRIDE;
    #pragma unroll
    for (int nt = 0; nt < 8; ++nt) {
        float2 v;
        v.x = o0[nt][0] * i00; v.y = o0[nt][1] * i00; *(float2*)(O + ra0 + nt*8 + 2*t) = v;
        v.x = o0[nt][2] * i01; v.y = o0[nt][3] * i01; *(float2*)(O + ra1 + nt*8 + 2*t) = v;
        v.x = o1[nt][0] * i10; v.y = o1[nt][1] * i10; *(float2*)(O + rb0 + nt*8 + 2*t) = v;
        v.x = o1[nt][2] * i11; v.y = o1[nt][3] * i11; *(float2*)(O + rb1 + nt*8 + 2*t) = v;
    }
}

extern "C" void kernel_launch(void* const* d_in, const int* in_sizes, int n_in,
                              void* d_out, int out_size)
{
    const float* Q = (const float*)d_in[0];
    const float* K = (const float*)d_in[1];
    const float* V = (const float*)d_in[2];
    float* O = (float*)d_out;

    cudaFuncSetAttribute(attn_f16x_kernel,
                         cudaFuncAttributeMaxDynamicSharedMemorySize, SMEM_BYTES);

    dim3 grid(Lc / LTILE, Bc * Nc * Hc);    // (8, 128)
    attn_f16x_kernel<<<grid, NTHREADS, SMEM_BYTES>>>(Q, K, V, O);
}

// round 11
// speedup vs baseline: 2.9122x; 1.2143x over previous
#include <cuda_runtime.h>
#include <cuda_fp16.h>
#include <math.h>
#include <stdint.h>

// [B,N,L,H,E] = [4,4,1024,8,64] fp32. For fixed (b,n,h): row l at bn*L*H*E + l*H*E + h*E,
// contiguous E=64 floats, stride H*E=512 floats between consecutive l.

#define Bc 4
#define Nc 4
#define Lc 1024
#define Hc 8
#define Ec 64
#define ROWSTRIDE (Hc*Ec)

#define LTILE 128
#define STILE 64
#define NTHREADS 128            // 4 warps, each owns 32 query rows (2 rowsets of 16)
#define PADH 72                 // smem pitch in halves: 144B -> conflict-free LDSM phases
#define NJOBS 1024              // 8 qt x 128 bnh
#define NCTAS 444               // 148 SMs x 3 resident CTAs

#define SQ_H (LTILE*PADH)       // 9216 halves
#define SK_H (STILE*PADH)       // 4608
#define SV_H (STILE*PADH)       // 4608
#define SMEM_BYTES ((SQ_H + SK_H + SV_H) * 2)   // 36864 B -> 3 CTAs/SM

// Q pre-scale: (1/sqrt(64)) * log2(e)  -> softmax in exp2 domain
#define QSCALE 0.18033688011111204f

__device__ int g_job_ctr;

extern "C" __global__ void reset_ctr_kernel() { g_job_ctr = 0; }

// D(16x8,f32) += A(16x16,f16,row) * B(16x8,f16,col)
static __device__ __forceinline__ void mma16(float* c, const uint32_t* a, const uint32_t* b) {
    asm volatile(
        "mma.sync.aligned.m16n8k16.row.col.f32.f16.f16.f32 "
        "{%0,%1,%2,%3}, {%4,%5,%6,%7}, {%8,%9}, {%0,%1,%2,%3};"
        : "+f"(c[0]), "+f"(c[1]), "+f"(c[2]), "+f"(c[3])
        : "r"(a[0]), "r"(a[1]), "r"(a[2]), "r"(a[3]), "r"(b[0]), "r"(b[1]));
}
static __device__ __forceinline__ void ldsm4(uint32_t* r, uint32_t addr) {
    asm volatile("ldmatrix.sync.aligned.m8n8.x4.shared.b16 {%0,%1,%2,%3}, [%4];"
                 : "=r"(r[0]), "=r"(r[1]), "=r"(r[2]), "=r"(r[3]) : "r"(addr));
}
static __device__ __forceinline__ void ldsm4t(uint32_t* r, uint32_t addr) {
    asm volatile("ldmatrix.sync.aligned.m8n8.x4.trans.shared.b16 {%0,%1,%2,%3}, [%4];"
                 : "=r"(r[0]), "=r"(r[1]), "=r"(r[2]), "=r"(r[3]) : "r"(addr));
}
static __device__ __forceinline__ float ex2(float x) {
    float y; asm("ex2.approx.f32 %0, %1;" : "=f"(y) : "f"(x)); return y;
}
static __device__ __forceinline__ uint32_t ex2h2(uint32_t x) {
    uint32_t y; asm("ex2.approx.f16x2 %0, %1;" : "=r"(y) : "r"(x)); return y;
}
static __device__ __forceinline__ uint32_t f2h2(float a, float b) {
    __half2 h = __floats2half2_rn(a, b);
    return *(uint32_t*)&h;
}
static __device__ __forceinline__ uint2 f4toh4(float4 v, float sc) {
    __half2 lo = __floats2half2_rn(v.x * sc, v.y * sc);
    __half2 hi = __floats2half2_rn(v.z * sc, v.w * sc);
    uint2 u;
    u.x = *(uint32_t*)&lo;  u.y = *(uint32_t*)&hi;
    return u;
}

// Online-softmax for one 16-row rowset: consumes f32 C-frags s[8][4], produces
// GEMM2 A-frags af[8][2] (f16x2 via ex2.approx.f16x2), updates m/l, rescales o.
// Row sums come from an extra tensor-core mma against ones.
static __device__ __forceinline__ void softmax_frag(
    float s[8][4], float& m0, float& m1, float& l0, float& l1,
    float o[8][4], uint32_t af[8][2])
{
    float mx0 = -INFINITY, mx1 = -INFINITY;
    #pragma unroll
    for (int nt = 0; nt < 8; ++nt) {
        mx0 = fmaxf(mx0, fmaxf(s[nt][0], s[nt][1]));
        mx1 = fmaxf(mx1, fmaxf(s[nt][2], s[nt][3]));
    }
    mx0 = fmaxf(mx0, __shfl_xor_sync(0xffffffffu, mx0, 1));
    mx0 = fmaxf(mx0, __shfl_xor_sync(0xffffffffu, mx0, 2));
    mx1 = fmaxf(mx1, __shfl_xor_sync(0xffffffffu, mx1, 1));
    mx1 = fmaxf(mx1, __shfl_xor_sync(0xffffffffu, mx1, 2));

    float mn0 = fmaxf(m0, mx0), mn1 = fmaxf(m1, mx1);
    float cr0 = ex2(m0 - mn0),  cr1 = ex2(m1 - mn1);

    #pragma unroll
    for (int nt = 0; nt < 8; ++nt) {
        af[nt][0] = ex2h2(f2h2(s[nt][0] - mn0, s[nt][1] - mn0));   // rows g (masked -inf -> 0)
        af[nt][1] = ex2h2(f2h2(s[nt][2] - mn1, s[nt][3] - mn1));   // rows g+8
    }

    float ls[4] = {0.f, 0.f, 0.f, 0.f};
    const uint32_t one2[2] = {0x3C003C00u, 0x3C003C00u};
    #pragma unroll
    for (int kk = 0; kk < 4; ++kk) {
        uint32_t a[4] = { af[2*kk][0], af[2*kk][1], af[2*kk+1][0], af[2*kk+1][1] };
        mma16(ls, a, one2);
    }

    l0 = l0 * cr0 + ls[0];
    l1 = l1 * cr1 + ls[2];
    m0 = mn0;  m1 = mn1;

    if (__ballot_sync(0xffffffffu, (cr0 != 1.f) | (cr1 != 1.f))) {
        #pragma unroll
        for (int nt = 0; nt < 8; ++nt) {
            o[nt][0] *= cr0; o[nt][1] *= cr0; o[nt][2] *= cr1; o[nt][3] *= cr1;
        }
    }
}

extern "C" __global__ void __launch_bounds__(NTHREADS, 3)
attn_persist_kernel(const float* __restrict__ Q, const float* __restrict__ K,
                    const float* __restrict__ V, float* __restrict__ O)
{
    extern __shared__ __half smem_h[];
    __half* sQ = smem_h;
    __half* sK = sQ + SQ_H;
    __half* sV = sK + SK_H;
    __shared__ int s_item;

    const int tid  = threadIdx.x;
    const int w    = tid >> 5;          // warp 0..3, owns query rows [w*32, w*32+32)
    const int lane = tid & 31;
    const int g    = lane >> 2;
    const int t    = lane & 3;

    const int lr = tid >> 4;            // 0..7 (fill row)
    const int le = (tid & 15) << 2;     // 0,4,..,60 (fill col, halves)

    // per-lane ldmatrix geometry (job-independent parts)
    const int rw  = w * 32;
    const int la7 = lane & 7;
    const int lb  = (lane >> 3) & 1;
    const int lc  = lane >> 4;
    const uint32_t qb = (uint32_t)__cvta_generic_to_shared(sQ);
    const uint32_t kb = (uint32_t)__cvta_generic_to_shared(sK);
    const uint32_t vb = (uint32_t)__cvta_generic_to_shared(sV);
    const uint32_t q_ls0 = qb + (uint32_t)(((rw +      la7 + 8 * lb) * PADH + 8 * lc) * 2);
    const uint32_t q_ls1 = qb + (uint32_t)(((rw + 16 + la7 + 8 * lb) * PADH + 8 * lc) * 2);
    const uint32_t k_ls = kb + (uint32_t)(((la7 + 8 * lc) * PADH + 8 * lb) * 2);
    const uint32_t v_ls = vb + (uint32_t)(((la7 + 8 * lb) * PADH + 8 * lc) * 2);

    while (true) {
        __syncthreads();                // prior job done with smem + s_item
        if (tid == 0) s_item = atomicAdd(&g_job_ctr, 1);
        __syncthreads();
        const int item = s_item;
        if (item >= NJOBS) break;

        // LPT order: heavy query-tiles (qt=7, 16 key-tiles) first
        const int qt  = 7 - (item >> 7);
        const int bnh = item & 127;
        const int h   = bnh & (Hc - 1);
        const int bn  = bnh >> 3;
        const size_t base = (size_t)bn * Lc * ROWSTRIDE + (size_t)h * Ec;
        const int q0 = qt * LTILE;

        // ---- Q tile -> smem as f16, pre-scaled by 1/sqrt(E)*log2(e) ----
        #pragma unroll
        for (int it = 0; it < LTILE / 8; ++it) {
            int r = it * 8 + lr;
            float4 v = *(const float4*)(Q + base + (size_t)(q0 + r) * ROWSTRIDE + le);
            *(uint2*)(&sQ[r * PADH + le]) = f4toh4(v, QSCALE);
        }

        float o0[8][4], o1[8][4];
        #pragma unroll
        for (int nt = 0; nt < 8; ++nt) {
            o0[nt][0]=0.f; o0[nt][1]=0.f; o0[nt][2]=0.f; o0[nt][3]=0.f;
            o1[nt][0]=0.f; o1[nt][1]=0.f; o1[nt][2]=0.f; o1[nt][3]=0.f;
        }
        float m00 = -INFINITY, m01 = -INFINITY, m10 = -INFINITY, m11 = -INFINITY;
        float l00 = 0.f, l01 = 0.f, l10 = 0.f, l11 = 0.f;

        const int r0a = q0 + rw + g;    // rowset0 groups: r0a, r0a+8
        const int r0b = r0a + 16;       // rowset1 groups: r0b, r0b+8
        const int nkt = 2 * qt + 2;     // causal: key tiles 0 .. 2qt+1

        for (int kt = 0; kt < nkt; ++kt) {
            const int k0 = kt * STILE;

            __syncthreads();            // previous iteration done reading sK/sV
            #pragma unroll
            for (int it = 0; it < STILE / 8; ++it) {
                int r = it * 8 + lr;
                size_t ga = base + (size_t)(k0 + r) * ROWSTRIDE + le;
                *(uint2*)(&sK[r * PADH + le]) = f4toh4(*(const float4*)(K + ga), 1.0f);
                *(uint2*)(&sV[r * PADH + le]) = f4toh4(*(const float4*)(V + ga), 1.0f);
            }
            __syncthreads();

            if (k0 > q0 + rw + 31) continue;   // warp fully above diagonal

            // ---- GEMM1: S(32x64) = Q_w(32x64) * K^T ----
            float s0[8][4], s1[8][4];
            #pragma unroll
            for (int nt = 0; nt < 8; ++nt) {
                s0[nt][0]=0.f; s0[nt][1]=0.f; s0[nt][2]=0.f; s0[nt][3]=0.f;
                s1[nt][0]=0.f; s1[nt][1]=0.f; s1[nt][2]=0.f; s1[nt][3]=0.f;
            }
            #pragma unroll
            for (int kk = 0; kk < 4; ++kk) {
                uint32_t a0[4], a1[4];
                ldsm4(a0, q_ls0 + kk * 32);
                ldsm4(a1, q_ls1 + kk * 32);
                #pragma unroll
                for (int np = 0; np < 4; ++np) {
                    uint32_t b[4]; ldsm4(b, k_ls + (uint32_t)(np * 16 * PADH * 2 + kk * 32));
                    mma16(s0[2*np],     a0, b);
                    mma16(s0[2*np + 1], a0, b + 2);
                    mma16(s1[2*np],     a1, b);
                    mma16(s1[2*np + 1], a1, b + 2);
                }
            }

            // ---- causal mask (S pre-scaled via Q) ----
            if (k0 + STILE - 1 > q0 + rw) {
                #pragma unroll
                for (int nt = 0; nt < 8; ++nt) {
                    int c = k0 + nt * 8 + 2 * t;
                    if (c     > r0a)     s0[nt][0] = -INFINITY;
                    if (c + 1 > r0a)     s0[nt][1] = -INFINITY;
                    if (c     > r0a + 8) s0[nt][2] = -INFINITY;
                    if (c + 1 > r0a + 8) s0[nt][3] = -INFINITY;
                    if (c     > r0b)     s1[nt][0] = -INFINITY;
                    if (c + 1 > r0b)     s1[nt][1] = -INFINITY;
                    if (c     > r0b + 8) s1[nt][2] = -INFINITY;
                    if (c + 1 > r0b + 8) s1[nt][3] = -INFINITY;
                }
            }

            // ---- online softmax per rowset ----
            uint32_t af0[8][2], af1[8][2];
            softmax_frag(s0, m00, m01, l00, l01, o0, af0);
            softmax_frag(s1, m10, m11, l10, l11, o1, af1);

            // ---- GEMM2: O(32x64) += P(32x64) * V(64x64) ----
            #pragma unroll
            for (int kk = 0; kk < 4; ++kk) {
                uint32_t a0[4] = { af0[2*kk][0], af0[2*kk][1], af0[2*kk+1][0], af0[2*kk+1][1] };
                uint32_t a1[4] = { af1[2*kk][0], af1[2*kk][1], af1[2*kk+1][0], af1[2*kk+1][1] };
                #pragma unroll
                for (int np = 0; np < 4; ++np) {
                    uint32_t b[4];
                    ldsm4t(b, v_ls + (uint32_t)(kk * 16 * PADH * 2 + np * 32));
                    mma16(o0[2*np],     a0, b);
                    mma16(o0[2*np + 1], a0, b + 2);
                    mma16(o1[2*np],     a1, b);
                    mma16(o1[2*np + 1], a1, b + 2);
                }
            }
        }

        // ---- epilogue: normalize, store 32 rows/warp ----
        const float i00 = 1.f / l00, i01 = 1.f / l01, i10 = 1.f / l10, i11 = 1.f / l11;
        const size_t ra0 = base + (size_t)r0a * ROWSTRIDE;
        const size_t ra1 = ra0 + (size_t)8 * ROWSTRIDE;
        const size_t rb0 = base + (size_t)r0b * ROWSTRIDE;
        const size_t rb1 = rb0 + (size_t)8 * ROWSTRIDE;
        #pragma unroll
        for (int nt = 0; nt < 8; ++nt) {
            float2 v;
            v.x = o0[nt][0] * i00; v.y = o0[nt][1] * i00; *(float2*)(O + ra0 + nt*8 + 2*t) = v;
            v.x = o0[nt][2] * i01; v.y = o0[nt][3] * i01; *(float2*)(O + ra1 + nt*8 + 2*t) = v;
            v.x = o1[nt][0] * i10; v.y = o1[nt][1] * i10; *(float2*)(O + rb0 + nt*8 + 2*t) = v;
            v.x = o1[nt][2] * i11; v.y = o1[nt][3] * i11; *(float2*)(O + rb1 + nt*8 + 2*t) = v;
        }
    }
}

extern "C" void kernel_launch(void* const* d_in, const int* in_sizes, int n_in,
                              void* d_out, int out_size)
{
    const float* Q = (const float*)d_in[0];
    const float* K = (const float*)d_in[1];
    const float* V = (const float*)d_in[2];
    float* O = (float*)d_out;

    cudaFuncSetAttribute(attn_persist_kernel,
                         cudaFuncAttributeMaxDynamicSharedMemorySize, SMEM_BYTES);

    reset_ctr_kernel<<<1, 1>>>();
    attn_persist_kernel<<<NCTAS, NTHREADS, SMEM_BYTES>>>(Q, K, V, O);
}